// round 13
// baseline (speedup 1.0000x reference)
#include <cuda_runtime.h>
#include <cstdint>

// TemporalPyramidPooling: overlapping masked window means at w=4/8/16, stride w/2.
// Hierarchical non-overlapping pair sums in packed f32x2.
// R13 = R12 + 2-CTA cluster DSMEM boundary exchange: rank1 pushes its first-group
//       partials into rank0's smem (mapa + st.shared::cluster + release-arrive);
//       rank0 computes the inter-tile boundary with NO gmem halo load.
//       Halo loads drop 25% -> 12.5% (only at cluster<->cluster seams, done by rank1).
//       No __syncthreads serialization: rank0's mbarrier wait lands ~3000 cyc after
//       the data arrived. 1-warp CTAs, GPB=4, DSPLIT=4, evict_last loads, cs stores.
//
//   x    [B=8, T=4096, D=512] f32
//   mask [B, T]  (bool; 1-byte or int32 0/1 -- detected at runtime)
// Outputs concatenated f32:
//   vis4 [B,2047,D], vis8 [B,1023,D], vis16 [B,511,D],
//   msk4 [B,2047],   msk8 [B,1023],   msk16 [B,511]

namespace {
constexpr int B   = 8;
constexpr int T   = 4096;
constexpr int D   = 512;
constexpr int D4  = D / 4;                  // 128 float4 lanes
constexpr int S4  = 2047;
constexpr int S8  = 1023;
constexpr int S16 = 511;
constexpr int NGROUPS = T / 8;              // 512 pair8 groups per batch
constexpr int GPB = 4;                      // groups per CTA tile (32 t)
constexpr int TILES_PER_B = NGROUPS / GPB;  // 128 tiles
constexpr int PAIRS_PER_B = TILES_PER_B / 2;// 64 cluster pairs
constexpr int DSPLIT = 4;                   // CTAs along D
constexpr int BLK = D4 / DSPLIT;            // 32 threads = 1 warp
}

__constant__ float c_inv[17] = {
    1e6f, 1.0f, 0.5f, 1.0f/3.0f, 0.25f, 0.2f, 1.0f/6.0f, 1.0f/7.0f,
    0.125f, 1.0f/9.0f, 0.1f, 1.0f/11.0f, 1.0f/12.0f, 1.0f/13.0f,
    1.0f/14.0f, 1.0f/15.0f, 0.0625f
};

// ---- packed f32x2 helpers (4 floats = 2 x u64) ----
struct P2 { uint64_t a, b; };

__device__ __forceinline__ uint64_t addx2(uint64_t x, uint64_t y) {
    uint64_t r; asm("add.rn.f32x2 %0, %1, %2;" : "=l"(r) : "l"(x), "l"(y)); return r;
}
__device__ __forceinline__ uint64_t mulx2(uint64_t x, uint64_t y) {
    uint64_t r; asm("mul.rn.f32x2 %0, %1, %2;" : "=l"(r) : "l"(x), "l"(y)); return r;
}
__device__ __forceinline__ uint64_t bcast2(float s) {
    uint64_t r; asm("mov.b64 %0, {%1, %1};" : "=l"(r) : "f"(s)); return r;
}
__device__ __forceinline__ P2 p2zero() { P2 r; r.a = 0ull; r.b = 0ull; return r; }
__device__ __forceinline__ P2 p2add(P2 x, P2 y) { P2 r; r.a = addx2(x.a, y.a); r.b = addx2(x.b, y.b); return r; }
__device__ __forceinline__ P2 p2scale(P2 x, float s) {
    const uint64_t s2 = bcast2(s);
    P2 r; r.a = mulx2(x.a, s2); r.b = mulx2(x.b, s2); return r;
}

__device__ __forceinline__ uint64_t make_evict_last_policy() {
    uint64_t pol;
    asm("createpolicy.fractional.L2::evict_last.b64 %0, 1.0;" : "=l"(pol));
    return pol;
}
__device__ __forceinline__ P2 ldg_el(const void* p, uint64_t pol) {
    P2 r;
    asm("ld.global.nc.L2::cache_hint.v2.b64 {%0,%1}, [%2], %3;"
        : "=l"(r.a), "=l"(r.b) : "l"(p), "l"(pol));
    return r;
}
__device__ __forceinline__ void stcs16(void* p, P2 v) {
    asm volatile("st.global.cs.v2.b64 [%0], {%1,%2};" :: "l"(p), "l"(v.a), "l"(v.b) : "memory");
}

// ---- cluster / DSMEM helpers ----
__device__ __forceinline__ uint32_t smem_u32(const void* p) {
    uint32_t r;
    asm("{ .reg .u64 t; cvta.to.shared.u64 t, %1; cvt.u32.u64 %0, t; }" : "=r"(r) : "l"(p));
    return r;
}
__device__ __forceinline__ uint32_t mapa_u32(uint32_t saddr, uint32_t rank) {
    uint32_t r;
    asm("mapa.shared::cluster.u32 %0, %1, %2;" : "=r"(r) : "r"(saddr), "r"(rank));
    return r;
}
__device__ __forceinline__ void st_cl_u64(uint32_t a, uint64_t v) {
    asm volatile("st.shared::cluster.u64 [%0], %1;" :: "r"(a), "l"(v) : "memory");
}
__device__ __forceinline__ void st_cl_u32(uint32_t a, unsigned v) {
    asm volatile("st.shared::cluster.u32 [%0], %1;" :: "r"(a), "r"(v) : "memory");
}
__device__ __forceinline__ void mbar_init(uint32_t a, unsigned cnt) {
    asm volatile("mbarrier.init.shared.b64 [%0], %1;" :: "r"(a), "r"(cnt) : "memory");
}
__device__ __forceinline__ void mbar_arrive_remote(uint32_t a) {
    asm volatile("mbarrier.arrive.release.cluster.shared::cluster.b64 _, [%0];" :: "r"(a) : "memory");
}
__device__ __forceinline__ void mbar_wait_acq_cluster(uint32_t a) {
    unsigned done;
    do {
        asm volatile(
            "{\n\t.reg .pred p;\n\t"
            "mbarrier.try_wait.parity.acquire.cluster.shared::cta.b64 p, [%1], %2;\n\t"
            "selp.b32 %0, 1, 0, p;\n\t}"
            : "=r"(done) : "r"(a), "r"(0u) : "memory");
    } while (!done);
}

struct GroupSums {
    P2 c0, c1, c2, c3;
    int n0, n1, n2, n3;
};

__device__ __forceinline__ GroupSums load_group(
    const char* __restrict__ xb, const void* __restrict__ mask_raw,
    bool mask_is_byte, int b, int g, uint64_t pol)
{
    const int t0 = g * 8;
    int mi[8];
    if (mask_is_byte) {
        const uint8_t* mb = (const uint8_t*)mask_raw + (size_t)b * T + t0;
        const uint64_t mw = *reinterpret_cast<const uint64_t*>(mb);
        #pragma unroll
        for (int i = 0; i < 8; ++i) mi[i] = (int)((mw >> (8 * i)) & 1u);
    } else {
        const int4* mw = reinterpret_cast<const int4*>(
            (const int*)mask_raw + (size_t)b * T + t0);
        int4 a = mw[0], c = mw[1];
        mi[0] = (a.x != 0); mi[1] = (a.y != 0); mi[2] = (a.z != 0); mi[3] = (a.w != 0);
        mi[4] = (c.x != 0); mi[5] = (c.y != 0); mi[6] = (c.z != 0); mi[7] = (c.w != 0);
    }

    P2 v[8];
    #pragma unroll
    for (int i = 0; i < 8; ++i)
        v[i] = ldg_el(xb + (size_t)(t0 + i) * (D4 * 16), pol);
    #pragma unroll
    for (int i = 0; i < 8; ++i) {
        v[i].a = mi[i] ? v[i].a : 0ull;
        v[i].b = mi[i] ? v[i].b : 0ull;
    }

    GroupSums s;
    s.c0 = p2add(v[0], v[1]); s.c1 = p2add(v[2], v[3]);
    s.c2 = p2add(v[4], v[5]); s.c3 = p2add(v[6], v[7]);
    s.n0 = mi[0] + mi[1]; s.n1 = mi[2] + mi[3];
    s.n2 = mi[4] + mi[5]; s.n3 = mi[6] + mi[7];
    return s;
}

// DSMEM exchange buffer (lives in rank0; rank1 mirrors the layout).
struct __align__(16) XBuf {
    uint64_t mbar;
    uint64_t pad;
    uint64_t data[BLK][6];   // per-lane: c0.a,c0.b,d0.a,d0.b,e.a,e.b
    unsigned cnts;           // n0 | m0<<8 | q<<16
};

__global__ void __cluster_dims__(2, 1, 1) __launch_bounds__(BLK, 32)
tpp_kernel(const char* __restrict__ x,
           const void* __restrict__ mask_raw,
           float* __restrict__ out)
{
    __shared__ XBuf xbuf;

    const int lane = threadIdx.x;
    const int blk  = blockIdx.x;                // 0..4095
    const unsigned rank = blk & 1;              // cluster rank (tile parity)
    const int rest  = blk >> 1;
    const int dpart = rest % DSPLIT;
    const int t2    = rest / DSPLIT;            // 0..511
    const int b     = t2 / PAIRS_PER_B;
    const int pair  = t2 % PAIRS_PER_B;
    const int tile  = pair * 2 + (int)rank;
    const int g0    = tile * GPB;
    const int d4    = dpart * BLK + lane;

    const uint32_t sb = smem_u32(&xbuf);

    // init own mbarrier (count = 32: every producer lane release-arrives)
    if (lane == 0) mbar_init(sb, 32u);
    // cluster barrier: peer's mbarrier init must be visible before remote arrives
    asm volatile("barrier.cluster.arrive.aligned;" ::: "memory");
    asm volatile("barrier.cluster.wait.aligned;" ::: "memory");

    const uint64_t pol = make_evict_last_policy();

    unsigned mv = ((const unsigned*)mask_raw)[lane];
    const bool mask_is_byte = __any_sync(0xffffffffu, mv > 1u);

    const char* xb = x + ((size_t)b * T * D4 + d4) * 16;

    char* const vis4  = (char*)out;
    char* const vis8  = vis4  + (size_t)B * S4  * D4 * 16;
    char* const vis16 = vis8  + (size_t)B * S8  * D4 * 16;
    float* const msk4 = out + (size_t)B * (S4 + S8 + S16) * D;
    float* const msk8 = msk4 + B * S4;
    float* const msk16= msk8 + B * S8;

    const bool writeMsk = (lane == 0) && (dpart == 0);

    P2  prev_c3 = p2zero(), prev_d1 = p2zero(), prev_e = p2zero();
    int prev_n3 = 0,        prev_m1 = 0,        prev_q = 0;

    #pragma unroll
    for (int k = 0; k < GPB; ++k) {
        const int g = g0 + k;
        const GroupSums s = load_group(xb, mask_raw, mask_is_byte, b, g, pol);
        const P2 d0 = p2add(s.c0, s.c1), d1 = p2add(s.c2, s.c3);
        const P2 e  = p2add(d0, d1);
        const int m0 = s.n0 + s.n1, m1 = s.n2 + s.n3;
        const int q  = m0 + m1;

        if (k == 0 && rank == 1) {
            // push first-group boundary partials into rank0's smem
            const uint32_t dst = mapa_u32(sb + 16 + lane * 48, 0u);
            st_cl_u64(dst +  0, s.c0.a); st_cl_u64(dst +  8, s.c0.b);
            st_cl_u64(dst + 16, d0.a);   st_cl_u64(dst + 24, d0.b);
            st_cl_u64(dst + 32, e.a);    st_cl_u64(dst + 40, e.b);
            if (lane == 0)
                st_cl_u32(mapa_u32(sb + 16 + BLK * 48, 0u),
                          (unsigned)(s.n0 | (m0 << 8) | (q << 16)));
            mbar_arrive_remote(mapa_u32(sb, 0u));   // per-lane release-arrive
        }

        if (k > 0) {
            {   // win4 at 4g-1
                const int si = 4 * g - 1;
                const int cnt = prev_n3 + s.n0;
                stcs16(vis4 + ((size_t)(b * S4 + si) * D4 + d4) * 16,
                       p2scale(p2add(prev_c3, s.c0), c_inv[cnt]));
                if (writeMsk) __stcs(&msk4[b * S4 + si], (cnt > 0) ? 1.0f : 0.0f);
            }
            {   // win8 at 2g-1
                const int h = 2 * g - 1;
                const int cnt = prev_m1 + m0;
                stcs16(vis8 + ((size_t)(b * S8 + h) * D4 + d4) * 16,
                       p2scale(p2add(prev_d1, d0), c_inv[cnt]));
                if (writeMsk) __stcs(&msk8[b * S8 + h], (cnt > 0) ? 1.0f : 0.0f);
            }
            {   // win16 at g-1
                const int cnt = prev_q + q;
                stcs16(vis16 + ((size_t)(b * S16 + (g - 1)) * D4 + d4) * 16,
                       p2scale(p2add(prev_e, e), c_inv[cnt]));
                if (writeMsk) __stcs(&msk16[b * S16 + (g - 1)], (cnt > 0) ? 1.0f : 0.0f);
            }
        }
        {   // in-tile outputs
            const int si = 4 * g;
            int cnt;
            cnt = s.n0 + s.n1;
            stcs16(vis4 + ((size_t)(b * S4 + si    ) * D4 + d4) * 16,
                   p2scale(d0, c_inv[cnt]));
            if (writeMsk) __stcs(&msk4[b * S4 + si    ], (cnt > 0) ? 1.0f : 0.0f);
            cnt = s.n1 + s.n2;
            stcs16(vis4 + ((size_t)(b * S4 + si + 1) * D4 + d4) * 16,
                   p2scale(p2add(s.c1, s.c2), c_inv[cnt]));
            if (writeMsk) __stcs(&msk4[b * S4 + si + 1], (cnt > 0) ? 1.0f : 0.0f);
            cnt = s.n2 + s.n3;
            stcs16(vis4 + ((size_t)(b * S4 + si + 2) * D4 + d4) * 16,
                   p2scale(d1, c_inv[cnt]));
            if (writeMsk) __stcs(&msk4[b * S4 + si + 2], (cnt > 0) ? 1.0f : 0.0f);

            const int h = 2 * g;
            cnt = m0 + m1;
            stcs16(vis8 + ((size_t)(b * S8 + h) * D4 + d4) * 16,
                   p2scale(e, c_inv[cnt]));
            if (writeMsk) __stcs(&msk8[b * S8 + h], (cnt > 0) ? 1.0f : 0.0f);
        }

        prev_c3 = s.c3; prev_d1 = d1; prev_e = e;
        prev_n3 = s.n3; prev_m1 = m1; prev_q = q;
    }

    const int gH = g0 + GPB;
    if (rank == 0) {
        // boundary into rank1's tile: partials arrive via DSMEM (no gmem halo)
        mbar_wait_acq_cluster(sb);
        P2 pc0, pd0, pe;
        pc0.a = xbuf.data[lane][0]; pc0.b = xbuf.data[lane][1];
        pd0.a = xbuf.data[lane][2]; pd0.b = xbuf.data[lane][3];
        pe.a  = xbuf.data[lane][4]; pe.b  = xbuf.data[lane][5];
        const unsigned pc = xbuf.cnts;
        const int p_n0 = pc & 0xff, p_m0 = (pc >> 8) & 0xff, p_q = (pc >> 16) & 0xff;

        {   // win4 at 4*gH-1
            const int si = 4 * gH - 1;
            const int cnt = prev_n3 + p_n0;
            stcs16(vis4 + ((size_t)(b * S4 + si) * D4 + d4) * 16,
                   p2scale(p2add(prev_c3, pc0), c_inv[cnt]));
            if (writeMsk) __stcs(&msk4[b * S4 + si], (cnt > 0) ? 1.0f : 0.0f);
        }
        {   // win8 at 2*gH-1
            const int h = 2 * gH - 1;
            const int cnt = prev_m1 + p_m0;
            stcs16(vis8 + ((size_t)(b * S8 + h) * D4 + d4) * 16,
                   p2scale(p2add(prev_d1, pd0), c_inv[cnt]));
            if (writeMsk) __stcs(&msk8[b * S8 + h], (cnt > 0) ? 1.0f : 0.0f);
        }
        {   // win16 at gH-1
            const int cnt = prev_q + p_q;
            stcs16(vis16 + ((size_t)(b * S16 + (gH - 1)) * D4 + d4) * 16,
                   p2scale(p2add(prev_e, pe), c_inv[cnt]));
            if (writeMsk) __stcs(&msk16[b * S16 + (gH - 1)], (cnt > 0) ? 1.0f : 0.0f);
        }
    } else if (gH < NGROUPS) {
        // cluster<->cluster seam: gmem halo load (1 per 8 groups)
        const GroupSums s = load_group(xb, mask_raw, mask_is_byte, b, gH, pol);
        const P2 d0 = p2add(s.c0, s.c1);
        const P2 e  = p2add(d0, p2add(s.c2, s.c3));
        const int m0 = s.n0 + s.n1;
        const int q  = m0 + s.n2 + s.n3;
        {   // win4 at 4*gH-1
            const int si = 4 * gH - 1;
            const int cnt = prev_n3 + s.n0;
            stcs16(vis4 + ((size_t)(b * S4 + si) * D4 + d4) * 16,
                   p2scale(p2add(prev_c3, s.c0), c_inv[cnt]));
            if (writeMsk) __stcs(&msk4[b * S4 + si], (cnt > 0) ? 1.0f : 0.0f);
        }
        {   // win8 at 2*gH-1
            const int h = 2 * gH - 1;
            const int cnt = prev_m1 + m0;
            stcs16(vis8 + ((size_t)(b * S8 + h) * D4 + d4) * 16,
                   p2scale(p2add(prev_d1, d0), c_inv[cnt]));
            if (writeMsk) __stcs(&msk8[b * S8 + h], (cnt > 0) ? 1.0f : 0.0f);
        }
        {   // win16 at gH-1
            const int cnt = prev_q + q;
            stcs16(vis16 + ((size_t)(b * S16 + (gH - 1)) * D4 + d4) * 16,
                   p2scale(p2add(prev_e, e), c_inv[cnt]));
            if (writeMsk) __stcs(&msk16[b * S16 + (gH - 1)], (cnt > 0) ? 1.0f : 0.0f);
        }
    }

    // no CTA may exit while its peer might still write into its smem:
    // rank0 has consumed; rank1's stores are complete before its arrive.
    // A final cluster barrier guarantees rank0's smem stays alive until
    // rank1's arrive has been consumed (it has: rank0 waited), and vice versa.
    asm volatile("barrier.cluster.arrive.aligned;" ::: "memory");
    asm volatile("barrier.cluster.wait.aligned;" ::: "memory");
}

extern "C" void kernel_launch(void* const* d_in, const int* in_sizes, int n_in,
                              void* d_out, int out_size)
{
    const char* x    = (const char*)d_in[0];
    const void* mask = (const void*)d_in[1];
    float*      out  = (float*)d_out;

    tpp_kernel<<<B * PAIRS_PER_B * DSPLIT * 2, BLK>>>(x, mask, out);
}

// round 14
// speedup vs baseline: 1.9331x; 1.9331x over previous
#include <cuda_runtime.h>
#include <cstdint>

// TemporalPyramidPooling: overlapping masked window means at w=4/8/16, stride w/2.
// Hierarchical non-overlapping pair sums in packed f32x2 (PTX add/mul.rn.f32x2).
// R14 = R12 structure with GPB=2: 8192 one-warp CTAs -> 32-CTA/SM slot cap -> ~50% occ
//       (the only lever that has ever moved this kernel is resident-warp count).
//       Halo rises to 50% but halo groups are L2-resident (read concurrently by the
//       neighboring CTA); L2 had ~40% headroom. DSPLIT=4, evict_last loads, cs stores.
//
//   x    [B=8, T=4096, D=512] f32
//   mask [B, T]  (bool; stored as 1-byte or int32 0/1 -- detected at runtime)
// Outputs concatenated f32:
//   vis4 [B,2047,D], vis8 [B,1023,D], vis16 [B,511,D],
//   msk4 [B,2047],   msk8 [B,1023],   msk16 [B,511]

namespace {
constexpr int B   = 8;
constexpr int T   = 4096;
constexpr int D   = 512;
constexpr int D4  = D / 4;                  // 128 float4 lanes
constexpr int S4  = 2047;
constexpr int S8  = 1023;
constexpr int S16 = 511;
constexpr int NGROUPS = T / 8;              // 512 pair8 groups per batch
constexpr int GPB = 2;                      // groups per block (tile = 16 t)
constexpr int BLOCKS_PER_B = NGROUPS / GPB; // 256
constexpr int DSPLIT = 4;                   // CTAs per (b, gtile) along D
constexpr int BLK = D4 / DSPLIT;            // 32 threads = 1 warp
}

// 1/max(count,1e-6) for counts 0..16 (count==0 -> sum==0, product 0 matches ref)
__constant__ float c_inv[17] = {
    1e6f, 1.0f, 0.5f, 1.0f/3.0f, 0.25f, 0.2f, 1.0f/6.0f, 1.0f/7.0f,
    0.125f, 1.0f/9.0f, 0.1f, 1.0f/11.0f, 1.0f/12.0f, 1.0f/13.0f,
    1.0f/14.0f, 1.0f/15.0f, 0.0625f
};

// ---- packed f32x2 helpers (4 floats = 2 x u64) ----
struct P2 { uint64_t a, b; };

__device__ __forceinline__ uint64_t addx2(uint64_t x, uint64_t y) {
    uint64_t r; asm("add.rn.f32x2 %0, %1, %2;" : "=l"(r) : "l"(x), "l"(y)); return r;
}
__device__ __forceinline__ uint64_t mulx2(uint64_t x, uint64_t y) {
    uint64_t r; asm("mul.rn.f32x2 %0, %1, %2;" : "=l"(r) : "l"(x), "l"(y)); return r;
}
__device__ __forceinline__ uint64_t bcast2(float s) {
    uint64_t r; asm("mov.b64 %0, {%1, %1};" : "=l"(r) : "f"(s)); return r;
}
__device__ __forceinline__ P2 p2zero() { P2 r; r.a = 0ull; r.b = 0ull; return r; }
__device__ __forceinline__ P2 p2add(P2 x, P2 y) { P2 r; r.a = addx2(x.a, y.a); r.b = addx2(x.b, y.b); return r; }
__device__ __forceinline__ P2 p2scale(P2 x, float s) {
    const uint64_t s2 = bcast2(s);
    P2 r; r.a = mulx2(x.a, s2); r.b = mulx2(x.b, s2); return r;
}

__device__ __forceinline__ uint64_t make_evict_last_policy() {
    uint64_t pol;
    asm("createpolicy.fractional.L2::evict_last.b64 %0, 1.0;" : "=l"(pol));
    return pol;
}
// 16B read-only load with L2 evict-last, directly into two f32x2 regs.
__device__ __forceinline__ P2 ldg_el(const void* p, uint64_t pol) {
    P2 r;
    asm("ld.global.nc.L2::cache_hint.v2.b64 {%0,%1}, [%2], %3;"
        : "=l"(r.a), "=l"(r.b) : "l"(p), "l"(pol));
    return r;
}
// 16B streaming (evict-first) store from two f32x2 regs.
__device__ __forceinline__ void stcs16(void* p, P2 v) {
    asm volatile("st.global.cs.v2.b64 [%0], {%1,%2};" :: "l"(p), "l"(v.a), "l"(v.b) : "memory");
}

struct GroupSums {
    P2 c0, c1, c2, c3;
    int n0, n1, n2, n3;
};

__device__ __forceinline__ GroupSums load_group(
    const char* __restrict__ xb, const void* __restrict__ mask_raw,
    bool mask_is_byte, int b, int g, uint64_t pol)
{
    const int t0 = g * 8;
    int mi[8];
    if (mask_is_byte) {
        const uint8_t* mb = (const uint8_t*)mask_raw + (size_t)b * T + t0;
        const uint64_t mw = *reinterpret_cast<const uint64_t*>(mb);
        #pragma unroll
        for (int i = 0; i < 8; ++i) mi[i] = (int)((mw >> (8 * i)) & 1u);
    } else {
        const int4* mw = reinterpret_cast<const int4*>(
            (const int*)mask_raw + (size_t)b * T + t0);
        int4 a = mw[0], c = mw[1];
        mi[0] = (a.x != 0); mi[1] = (a.y != 0); mi[2] = (a.z != 0); mi[3] = (a.w != 0);
        mi[4] = (c.x != 0); mi[5] = (c.y != 0); mi[6] = (c.z != 0); mi[7] = (c.w != 0);
    }

    P2 v[8];
    #pragma unroll
    for (int i = 0; i < 8; ++i)
        v[i] = ldg_el(xb + (size_t)(t0 + i) * (D4 * 16), pol);
    #pragma unroll
    for (int i = 0; i < 8; ++i) {
        v[i].a = mi[i] ? v[i].a : 0ull;   // zero-select == x * mask_f (ref semantics)
        v[i].b = mi[i] ? v[i].b : 0ull;
    }

    GroupSums s;
    s.c0 = p2add(v[0], v[1]); s.c1 = p2add(v[2], v[3]);
    s.c2 = p2add(v[4], v[5]); s.c3 = p2add(v[6], v[7]);
    s.n0 = mi[0] + mi[1]; s.n1 = mi[2] + mi[3];
    s.n2 = mi[4] + mi[5]; s.n3 = mi[6] + mi[7];
    return s;
}

__global__ void __launch_bounds__(BLK, 32)
tpp_kernel(const char* __restrict__ x,
           const void* __restrict__ mask_raw,
           float* __restrict__ out)
{
    const int blk   = blockIdx.x;               // 0..8191
    const int dpart = blk % DSPLIT;             // adjacent CTAs share the tile
    const int tile  = blk / DSPLIT;             // 0..2047
    const int b     = tile / BLOCKS_PER_B;
    const int g0    = (tile % BLOCKS_PER_B) * GPB;
    const int d4    = dpart * BLK + threadIdx.x;   // 0..127

    const uint64_t pol = make_evict_last_policy();

    // ---- mask storage-layout detection (byte vs int32), warp-uniform ----
    unsigned w = ((const unsigned*)mask_raw)[threadIdx.x];
    const bool mask_is_byte = __any_sync(0xffffffffu, w > 1u);

    const char* xb = x + ((size_t)b * T * D4 + d4) * 16;

    char* const vis4  = (char*)out;
    char* const vis8  = vis4  + (size_t)B * S4  * D4 * 16;
    char* const vis16 = vis8  + (size_t)B * S8  * D4 * 16;
    float* const msk4 = out + (size_t)B * (S4 + S8 + S16) * D;
    float* const msk8 = msk4 + B * S4;
    float* const msk16= msk8 + B * S8;

    const bool writeMsk = (threadIdx.x == 0) && (dpart == 0);

    P2  prev_c3 = p2zero(), prev_d1 = p2zero(), prev_e = p2zero();
    int prev_n3 = 0,        prev_m1 = 0,        prev_q = 0;

    const int gEnd = g0 + GPB;
    const int gLast = (gEnd < NGROUPS) ? gEnd : (gEnd - 1);

    for (int g = g0; g <= gLast; ++g) {          // rolled loop: smaller live set
        const GroupSums s = load_group(xb, mask_raw, mask_is_byte, b, g, pol);
        const P2 d0 = p2add(s.c0, s.c1), d1 = p2add(s.c2, s.c3);
        const P2 e  = p2add(d0, d1);
        const int m0 = s.n0 + s.n1, m1 = s.n2 + s.n3;
        const int q  = m0 + m1;

        if (g > g0) {
            {   // win4 at 4g-1 (crosses group boundary)
                const int si = 4 * g - 1;
                const int cnt = prev_n3 + s.n0;
                stcs16(vis4 + ((size_t)(b * S4 + si) * D4 + d4) * 16,
                       p2scale(p2add(prev_c3, s.c0), c_inv[cnt]));
                if (writeMsk) __stcs(&msk4[b * S4 + si], (cnt > 0) ? 1.0f : 0.0f);
            }
            {   // win8 at 2g-1
                const int h = 2 * g - 1;
                const int cnt = prev_m1 + m0;
                stcs16(vis8 + ((size_t)(b * S8 + h) * D4 + d4) * 16,
                       p2scale(p2add(prev_d1, d0), c_inv[cnt]));
                if (writeMsk) __stcs(&msk8[b * S8 + h], (cnt > 0) ? 1.0f : 0.0f);
            }
            {   // win16 at g-1
                const int cnt = prev_q + q;
                stcs16(vis16 + ((size_t)(b * S16 + (g - 1)) * D4 + d4) * 16,
                       p2scale(p2add(prev_e, e), c_inv[cnt]));
                if (writeMsk) __stcs(&msk16[b * S16 + (g - 1)], (cnt > 0) ? 1.0f : 0.0f);
            }
        }
        if (g < gEnd) {   // in-tile outputs
            const int si = 4 * g;
            int cnt;
            cnt = s.n0 + s.n1;
            stcs16(vis4 + ((size_t)(b * S4 + si    ) * D4 + d4) * 16,
                   p2scale(d0, c_inv[cnt]));
            if (writeMsk) __stcs(&msk4[b * S4 + si    ], (cnt > 0) ? 1.0f : 0.0f);
            cnt = s.n1 + s.n2;
            stcs16(vis4 + ((size_t)(b * S4 + si + 1) * D4 + d4) * 16,
                   p2scale(p2add(s.c1, s.c2), c_inv[cnt]));
            if (writeMsk) __stcs(&msk4[b * S4 + si + 1], (cnt > 0) ? 1.0f : 0.0f);
            cnt = s.n2 + s.n3;
            stcs16(vis4 + ((size_t)(b * S4 + si + 2) * D4 + d4) * 16,
                   p2scale(d1, c_inv[cnt]));
            if (writeMsk) __stcs(&msk4[b * S4 + si + 2], (cnt > 0) ? 1.0f : 0.0f);

            const int h = 2 * g;
            cnt = m0 + m1;
            stcs16(vis8 + ((size_t)(b * S8 + h) * D4 + d4) * 16,
                   p2scale(e, c_inv[cnt]));
            if (writeMsk) __stcs(&msk8[b * S8 + h], (cnt > 0) ? 1.0f : 0.0f);
        }

        prev_c3 = s.c3; prev_d1 = d1; prev_e = e;
        prev_n3 = s.n3; prev_m1 = m1; prev_q = q;
    }
}

extern "C" void kernel_launch(void* const* d_in, const int* in_sizes, int n_in,
                              void* d_out, int out_size)
{
    const char* x    = (const char*)d_in[0];
    const void* mask = (const void*)d_in[1];
    float*      out  = (float*)d_out;

    tpp_kernel<<<B * BLOCKS_PER_B * DSPLIT, BLK>>>(x, mask, out);
}

// round 15
// speedup vs baseline: 1.9560x; 1.0118x over previous
#include <cuda_runtime.h>
#include <cstdint>

// TemporalPyramidPooling: overlapping masked window means at w=4/8/16, stride w/2.
// Hierarchical non-overlapping pair sums in packed f32x2 (PTX add/mul.rn.f32x2).
// FINAL (= R12, best measured 18.91us): 1-warp CTAs, GPB=4, DSPLIT=4,
//   evict_last x loads (createpolicy + ld.global.nc.L2::cache_hint.v2.b64),
//   streaming evict-first stores (st.global.cs), reciprocal LUT for masked means.
// Lever ledger (R3-R14): vectorize +12%, occupancy +22%, D-split +9%; MLP pipeline,
//   f32x2, reg pressure all neutral; halo removal via smem/cluster regressed.
//   ~7.4 TB/s combined L2-level throughput = machine floor for this pattern.
//
//   x    [B=8, T=4096, D=512] f32
//   mask [B, T]  (bool; stored as 1-byte or int32 0/1 -- detected at runtime)
// Outputs concatenated f32:
//   vis4 [B,2047,D], vis8 [B,1023,D], vis16 [B,511,D],
//   msk4 [B,2047],   msk8 [B,1023],   msk16 [B,511]

namespace {
constexpr int B   = 8;
constexpr int T   = 4096;
constexpr int D   = 512;
constexpr int D4  = D / 4;                  // 128 float4 lanes
constexpr int S4  = 2047;
constexpr int S8  = 1023;
constexpr int S16 = 511;
constexpr int NGROUPS = T / 8;              // 512 pair8 groups per batch
constexpr int GPB = 4;                      // groups per block (tile = 32 t)
constexpr int BLOCKS_PER_B = NGROUPS / GPB; // 128
constexpr int DSPLIT = 4;                   // CTAs per (b, gtile) along D
constexpr int BLK = D4 / DSPLIT;            // 32 threads = 1 warp
}

// 1/max(count,1e-6) for counts 0..16 (count==0 -> sum==0, product 0 matches ref)
__constant__ float c_inv[17] = {
    1e6f, 1.0f, 0.5f, 1.0f/3.0f, 0.25f, 0.2f, 1.0f/6.0f, 1.0f/7.0f,
    0.125f, 1.0f/9.0f, 0.1f, 1.0f/11.0f, 1.0f/12.0f, 1.0f/13.0f,
    1.0f/14.0f, 1.0f/15.0f, 0.0625f
};

// ---- packed f32x2 helpers (4 floats = 2 x u64) ----
struct P2 { uint64_t a, b; };

__device__ __forceinline__ uint64_t addx2(uint64_t x, uint64_t y) {
    uint64_t r; asm("add.rn.f32x2 %0, %1, %2;" : "=l"(r) : "l"(x), "l"(y)); return r;
}
__device__ __forceinline__ uint64_t mulx2(uint64_t x, uint64_t y) {
    uint64_t r; asm("mul.rn.f32x2 %0, %1, %2;" : "=l"(r) : "l"(x), "l"(y)); return r;
}
__device__ __forceinline__ uint64_t bcast2(float s) {
    uint64_t r; asm("mov.b64 %0, {%1, %1};" : "=l"(r) : "f"(s)); return r;
}
__device__ __forceinline__ P2 p2zero() { P2 r; r.a = 0ull; r.b = 0ull; return r; }
__device__ __forceinline__ P2 p2add(P2 x, P2 y) { P2 r; r.a = addx2(x.a, y.a); r.b = addx2(x.b, y.b); return r; }
__device__ __forceinline__ P2 p2scale(P2 x, float s) {
    const uint64_t s2 = bcast2(s);
    P2 r; r.a = mulx2(x.a, s2); r.b = mulx2(x.b, s2); return r;
}

__device__ __forceinline__ uint64_t make_evict_last_policy() {
    uint64_t pol;
    asm("createpolicy.fractional.L2::evict_last.b64 %0, 1.0;" : "=l"(pol));
    return pol;
}
// 16B read-only load with L2 evict-last, directly into two f32x2 regs.
__device__ __forceinline__ P2 ldg_el(const void* p, uint64_t pol) {
    P2 r;
    asm("ld.global.nc.L2::cache_hint.v2.b64 {%0,%1}, [%2], %3;"
        : "=l"(r.a), "=l"(r.b) : "l"(p), "l"(pol));
    return r;
}
// 16B streaming (evict-first) store from two f32x2 regs.
__device__ __forceinline__ void stcs16(void* p, P2 v) {
    asm volatile("st.global.cs.v2.b64 [%0], {%1,%2};" :: "l"(p), "l"(v.a), "l"(v.b) : "memory");
}

// Per-group state kept live across the boundary stitch: pair2 sums + counts only
// (pair4/pair8 sums recomputed where needed -- one packed add each, saves regs).
struct GroupSums {
    P2 c0, c1, c2, c3;
    int n0, n1, n2, n3;
};

__device__ __forceinline__ GroupSums load_group(
    const char* __restrict__ xb, const void* __restrict__ mask_raw,
    bool mask_is_byte, int b, int g, uint64_t pol)
{
    const int t0 = g * 8;
    int mi[8];
    if (mask_is_byte) {
        const uint8_t* mb = (const uint8_t*)mask_raw + (size_t)b * T + t0;
        const uint64_t mw = *reinterpret_cast<const uint64_t*>(mb);
        #pragma unroll
        for (int i = 0; i < 8; ++i) mi[i] = (int)((mw >> (8 * i)) & 1u);
    } else {
        const int4* mw = reinterpret_cast<const int4*>(
            (const int*)mask_raw + (size_t)b * T + t0);
        int4 a = mw[0], c = mw[1];
        mi[0] = (a.x != 0); mi[1] = (a.y != 0); mi[2] = (a.z != 0); mi[3] = (a.w != 0);
        mi[4] = (c.x != 0); mi[5] = (c.y != 0); mi[6] = (c.z != 0); mi[7] = (c.w != 0);
    }

    P2 v[8];
    #pragma unroll
    for (int i = 0; i < 8; ++i)
        v[i] = ldg_el(xb + (size_t)(t0 + i) * (D4 * 16), pol);
    #pragma unroll
    for (int i = 0; i < 8; ++i) {
        v[i].a = mi[i] ? v[i].a : 0ull;   // zero-select == x * mask_f (ref semantics)
        v[i].b = mi[i] ? v[i].b : 0ull;
    }

    GroupSums s;
    s.c0 = p2add(v[0], v[1]); s.c1 = p2add(v[2], v[3]);
    s.c2 = p2add(v[4], v[5]); s.c3 = p2add(v[6], v[7]);
    s.n0 = mi[0] + mi[1]; s.n1 = mi[2] + mi[3];
    s.n2 = mi[4] + mi[5]; s.n3 = mi[6] + mi[7];
    return s;
}

__global__ void __launch_bounds__(BLK, 32)
tpp_kernel(const char* __restrict__ x,
           const void* __restrict__ mask_raw,
           float* __restrict__ out)
{
    const int blk   = blockIdx.x;               // 0..4095
    const int dpart = blk % DSPLIT;             // adjacent CTAs share the tile
    const int tile  = blk / DSPLIT;             // 0..1023
    const int b     = tile / BLOCKS_PER_B;
    const int g0    = (tile % BLOCKS_PER_B) * GPB;
    const int d4    = dpart * BLK + threadIdx.x;   // 0..127

    const uint64_t pol = make_evict_last_policy();

    // ---- mask storage-layout detection (byte vs int32), warp-uniform ----
    unsigned w = ((const unsigned*)mask_raw)[threadIdx.x];
    const bool mask_is_byte = __any_sync(0xffffffffu, w > 1u);

    const char* xb = x + ((size_t)b * T * D4 + d4) * 16;

    char* const vis4  = (char*)out;
    char* const vis8  = vis4  + (size_t)B * S4  * D4 * 16;
    char* const vis16 = vis8  + (size_t)B * S8  * D4 * 16;
    float* const msk4 = out + (size_t)B * (S4 + S8 + S16) * D;
    float* const msk8 = msk4 + B * S4;
    float* const msk16= msk8 + B * S8;

    const bool writeMsk = (threadIdx.x == 0) && (dpart == 0);

    P2  prev_c3 = p2zero(), prev_d1 = p2zero(), prev_e = p2zero();
    int prev_n3 = 0,        prev_m1 = 0,        prev_q = 0;

    const int gEnd = g0 + GPB;
    const int gLast = (gEnd < NGROUPS) ? gEnd : (gEnd - 1);

    for (int g = g0; g <= gLast; ++g) {          // rolled loop: smaller live set
        const GroupSums s = load_group(xb, mask_raw, mask_is_byte, b, g, pol);
        const P2 d0 = p2add(s.c0, s.c1), d1 = p2add(s.c2, s.c3);
        const P2 e  = p2add(d0, d1);
        const int m0 = s.n0 + s.n1, m1 = s.n2 + s.n3;
        const int q  = m0 + m1;

        if (g > g0) {
            {   // win4 at 4g-1 (crosses group boundary)
                const int si = 4 * g - 1;
                const int cnt = prev_n3 + s.n0;
                stcs16(vis4 + ((size_t)(b * S4 + si) * D4 + d4) * 16,
                       p2scale(p2add(prev_c3, s.c0), c_inv[cnt]));
                if (writeMsk) __stcs(&msk4[b * S4 + si], (cnt > 0) ? 1.0f : 0.0f);
            }
            {   // win8 at 2g-1
                const int h = 2 * g - 1;
                const int cnt = prev_m1 + m0;
                stcs16(vis8 + ((size_t)(b * S8 + h) * D4 + d4) * 16,
                       p2scale(p2add(prev_d1, d0), c_inv[cnt]));
                if (writeMsk) __stcs(&msk8[b * S8 + h], (cnt > 0) ? 1.0f : 0.0f);
            }
            {   // win16 at g-1
                const int cnt = prev_q + q;
                stcs16(vis16 + ((size_t)(b * S16 + (g - 1)) * D4 + d4) * 16,
                       p2scale(p2add(prev_e, e), c_inv[cnt]));
                if (writeMsk) __stcs(&msk16[b * S16 + (g - 1)], (cnt > 0) ? 1.0f : 0.0f);
            }
        }
        if (g < gEnd) {   // in-tile outputs
            const int si = 4 * g;
            int cnt;
            cnt = s.n0 + s.n1;
            stcs16(vis4 + ((size_t)(b * S4 + si    ) * D4 + d4) * 16,
                   p2scale(d0, c_inv[cnt]));
            if (writeMsk) __stcs(&msk4[b * S4 + si    ], (cnt > 0) ? 1.0f : 0.0f);
            cnt = s.n1 + s.n2;
            stcs16(vis4 + ((size_t)(b * S4 + si + 1) * D4 + d4) * 16,
                   p2scale(p2add(s.c1, s.c2), c_inv[cnt]));
            if (writeMsk) __stcs(&msk4[b * S4 + si + 1], (cnt > 0) ? 1.0f : 0.0f);
            cnt = s.n2 + s.n3;
            stcs16(vis4 + ((size_t)(b * S4 + si + 2) * D4 + d4) * 16,
                   p2scale(d1, c_inv[cnt]));
            if (writeMsk) __stcs(&msk4[b * S4 + si + 2], (cnt > 0) ? 1.0f : 0.0f);

            const int h = 2 * g;
            cnt = m0 + m1;
            stcs16(vis8 + ((size_t)(b * S8 + h) * D4 + d4) * 16,
                   p2scale(e, c_inv[cnt]));
            if (writeMsk) __stcs(&msk8[b * S8 + h], (cnt > 0) ? 1.0f : 0.0f);
        }

        prev_c3 = s.c3; prev_d1 = d1; prev_e = e;
        prev_n3 = s.n3; prev_m1 = m1; prev_q = q;
    }
}

extern "C" void kernel_launch(void* const* d_in, const int* in_sizes, int n_in,
                              void* d_out, int out_size)
{
    const char* x    = (const char*)d_in[0];
    const void* mask = (const void*)d_in[1];
    float*      out  = (float*)d_out;

    tpp_kernel<<<B * BLOCKS_PER_B * DSPLIT, BLK>>>(x, mask, out);
}